// round 17
// baseline (speedup 1.0000x reference)
#include <cuda_runtime.h>
#include <cuda_bf16.h>

// CrossNetwork (DCN-v1): x_{l+1} = input * (x_l . w_l) + x_l + b_l, L=6.
//
// Closed form: x_l = alpha_l*input + y_l,  y_l = sum_{j<l} b_j,
//   p_l = input.w_l, q_l = y_l.w_l,  alpha_{l+1} = alpha_l*(1+p_l)+q_l,
//   out = alpha_L*input + y_L.
//
// Round 17: TRANSPOSED decomposition. Thread tid owns dims [4t,4t+4) of
// every row -> W (6 float4), y (1 float4), q (6 floats) live in REGISTERS.
// Per row: 1 LDG.128 + 24 FMA + reduction + 1 STG.128 per thread. The 48
// LDS.128/pair of W traffic (the dominant LSU structural cost in all prior
// versions) is GONE. Block-level reduction via butterfly + 384B smem
// exchange, 2 barriers/pair. Persistent blocks, block-level pair stealing,
// next pair's input prefetched one iteration ahead.

#define D 1024
#define L 6
#define NTHREADS 256
#define NWARPS_B (NTHREADS / 32)     // 8
#define D4 (D / 4)                   // 256 float4 per row == NTHREADS
#define GRID_CTAS 444                // 148 SMs * 3 resident CTAs

__device__ unsigned int g_pair_ctr = 0;
__device__ unsigned int g_done_ctr = 0;

__device__ __forceinline__ float dot4(float4 a, float4 w, float acc) {
    acc = fmaf(a.x, w.x, acc);
    acc = fmaf(a.y, w.y, acc);
    acc = fmaf(a.z, w.z, acc);
    acc = fmaf(a.w, w.w, acc);
    return acc;
}

__global__ __launch_bounds__(NTHREADS, 3)
void crossnet_kernel(const float* __restrict__ input,
                     const float* __restrict__ Wg,
                     const float* __restrict__ bg,
                     float* __restrict__ out,
                     int B, int npairs, int nblocks)
{
    __shared__ float s_part[NWARPS_B][12];   // per-warp partials (2 rows x 6)
    __shared__ float s_alpha[2];
    __shared__ float s_q[L];
    __shared__ unsigned int s_pair;

    const int tid  = threadIdx.x;
    const int lane = tid & 31;
    const int warp = tid >> 5;

    // ---- W, y into registers (thread owns float4 column group tid) ----
    const float4* W4 = reinterpret_cast<const float4*>(Wg);
    const float4* B4 = reinterpret_cast<const float4*>(bg);
    float4 w[L];
#pragma unroll
    for (int l = 0; l < L; l++)
        w[l] = W4[l * D4 + tid];

    // y_L and per-thread q partials (q_l = y_l . w_l, y_l = prefix sum of b)
    float4 y = make_float4(0.f, 0.f, 0.f, 0.f);
    {
        float qp[L];
#pragma unroll
        for (int l = 0; l < L; l++) {
            qp[l] = dot4(y, w[l], 0.f);
            float4 bb = B4[l * D4 + tid];
            y.x += bb.x; y.y += bb.y; y.z += bb.z; y.w += bb.w;
        }
        // block-reduce the 6 q partials
#pragma unroll
        for (int l = 0; l < L; l++) {
#pragma unroll
            for (int o = 16; o > 0; o >>= 1)
                qp[l] += __shfl_xor_sync(0xffffffffu, qp[l], o);
        }
        if (lane == 0) {
#pragma unroll
            for (int l = 0; l < L; l++)
                s_part[warp][l] = qp[l];
        }
        __syncthreads();
        if (warp == 0 && lane < L) {
            float s = 0.f;
#pragma unroll
            for (int wv = 0; wv < NWARPS_B; wv++)
                s += s_part[wv][lane];
            s_q[lane] = s;
        }
        __syncthreads();
    }
    float q[L];
#pragma unroll
    for (int l = 0; l < L; l++) q[l] = s_q[l];

    const float4* inp  = reinterpret_cast<const float4*>(input);
    float4*       outp = reinterpret_cast<float4*>(out);

    // ---- prologue: pop first pair, load its input ----
    if (tid == 0) s_pair = atomicAdd(&g_pair_ctr, 1u);
    __syncthreads();
    unsigned int v = s_pair;
    __syncthreads();   // allow s_pair rewrite next iteration

    float4 in0 = make_float4(0.f, 0.f, 0.f, 0.f);
    float4 in1 = make_float4(0.f, 0.f, 0.f, 0.f);
    if (v < (unsigned int)npairs) {
        const int row0 = 2 * (int)v;
        in0 = inp[(size_t)row0 * D4 + tid];
        if (row0 + 1 < B) in1 = inp[(size_t)(row0 + 1) * D4 + tid];
    }

    while (v < (unsigned int)npairs) {
        const int row0 = 2 * (int)v;
        const bool r1ok = (row0 + 1 < B);

        // per-thread partial dots: 12 values (2 rows x 6 layers)
        float a0[L], a1[L];
#pragma unroll
        for (int l = 0; l < L; l++) {
            a0[l] = dot4(in0, w[l], 0.f);
            a1[l] = dot4(in1, w[l], 0.f);
        }

        // warp butterfly on 12 values
#pragma unroll
        for (int l = 0; l < L; l++) {
#pragma unroll
            for (int o = 16; o > 0; o >>= 1) {
                a0[l] += __shfl_xor_sync(0xffffffffu, a0[l], o);
                a1[l] += __shfl_xor_sync(0xffffffffu, a1[l], o);
            }
        }
        if (lane == 0) {
#pragma unroll
            for (int l = 0; l < L; l++) {
                s_part[warp][l]     = a0[l];
                s_part[warp][6 + l] = a1[l];
            }
        }

        // pop NEXT pair (overlaps with barrier)
        if (tid == 0) s_pair = atomicAdd(&g_pair_ctr, 1u);
        __syncthreads();   // B1: partials + next pair visible

        // warp0: cross-warp sum + scalar recurrence
        if (warp == 0) {
            float s = 0.f;
            if (lane < 12) {
#pragma unroll
                for (int wv = 0; wv < NWARPS_B; wv++)
                    s += s_part[wv][lane];
            }
            float aa0 = 1.0f, aa1 = 1.0f;
#pragma unroll
            for (int l = 0; l < L; l++) {
                float p0 = __shfl_sync(0xffffffffu, s, l);
                float p1 = __shfl_sync(0xffffffffu, s, 6 + l);
                aa0 = fmaf(aa0, p0, aa0) + q[l];
                aa1 = fmaf(aa1, p1, aa1) + q[l];
            }
            if (lane == 0) { s_alpha[0] = aa0; s_alpha[1] = aa1; }
        }
        unsigned int vn = s_pair;   // read between B1 and B2 (safe)
        __syncthreads();   // B2: alphas visible

        const float al0 = s_alpha[0];
        const float al1 = s_alpha[1];

        // prefetch next pair's input (latency hides under stores)
        float4 f0 = make_float4(0.f, 0.f, 0.f, 0.f);
        float4 f1 = make_float4(0.f, 0.f, 0.f, 0.f);
        if (vn < (unsigned int)npairs) {
            const int nr0 = 2 * (int)vn;
            f0 = inp[(size_t)nr0 * D4 + tid];
            if (nr0 + 1 < B) f1 = inp[(size_t)(nr0 + 1) * D4 + tid];
        }

        // epilogue: out = alpha * input + y_L
        float4 r0;
        r0.x = fmaf(al0, in0.x, y.x);
        r0.y = fmaf(al0, in0.y, y.y);
        r0.z = fmaf(al0, in0.z, y.z);
        r0.w = fmaf(al0, in0.w, y.w);
        outp[(size_t)row0 * D4 + tid] = r0;
        if (r1ok) {
            float4 r1;
            r1.x = fmaf(al1, in1.x, y.x);
            r1.y = fmaf(al1, in1.y, y.y);
            r1.z = fmaf(al1, in1.z, y.z);
            r1.w = fmaf(al1, in1.w, y.w);
            outp[(size_t)(row0 + 1) * D4 + tid] = r1;
        }

        in0 = f0; in1 = f1;
        v = vn;
    }

    // ---- reset counters for next graph replay (last block out) ----
    __syncthreads();
    if (tid == 0) {
        __threadfence();
        unsigned int d = atomicAdd(&g_done_ctr, 1u);
        if (d == (unsigned int)nblocks - 1u) {
            atomicExch(&g_pair_ctr, 0u);
            atomicExch(&g_done_ctr, 0u);
        }
    }
}

extern "C" void kernel_launch(void* const* d_in, const int* in_sizes, int n_in,
                              void* d_out, int out_size)
{
    const float* input = (const float*)d_in[0];
    const float* W     = (const float*)d_in[1];
    const float* b     = (const float*)d_in[2];
    float* out         = (float*)d_out;

    const int B      = in_sizes[0] / D;          // 16384
    const int npairs = (B + 1) / 2;              // 8192
    int grid         = GRID_CTAS;                // 444
    if (grid > npairs) grid = npairs;

    crossnet_kernel<<<grid, NTHREADS>>>(input, W, b, out, B, npairs, grid);
}